// round 3
// baseline (speedup 1.0000x reference)
#include <cuda_runtime.h>

// ---------------------------------------------------------------------------
// NCA step:  p = depthwise [ident, sobel_x, sobel_y] (16ch -> 48ch)
//            h = relu(W1 p + b1)   (48 -> 128)
//            dx = W2 h             (128 -> 16)
//            x_new = x + dx * update_mask
//            out   = x_new * (maxpool3(x[3])>0.1 & maxpool3(x_new[3])>0.1)
// ---------------------------------------------------------------------------

#define Bn  32
#define Cn  16
#define Hn  256
#define Wn  256
#define HCH 128
#define THRESH 0.1f

// 134 MB scratch for x_new (device global: allocation-free rule)
__device__ float g_xnew[Bn * Cn * Hn * Wn];

typedef unsigned long long u64;

__device__ __forceinline__ u64 fma2(u64 a, u64 b, u64 c) {
    u64 d;
    asm("fma.rn.f32x2 %0, %1, %2, %3;" : "=l"(d) : "l"(a), "l"(b), "l"(c));
    return d;
}
__device__ __forceinline__ u64 add2(u64 a, u64 b) {
    u64 d;
    asm("add.rn.f32x2 %0, %1, %2;" : "=l"(d) : "l"(a), "l"(b));
    return d;
}
__device__ __forceinline__ u64 pack2(float lo, float hi) {
    u64 d;
    asm("mov.b64 %0, {%1, %2};" : "=l"(d) : "f"(lo), "f"(hi));
    return d;
}
__device__ __forceinline__ void unpack2(u64 v, float& lo, float& hi) {
    asm("mov.b64 {%0, %1}, %2;" : "=f"(lo), "=f"(hi) : "l"(v));
}

// ---------------------------------------------------------------------------
// Kernel 1: perception + MLP + masked residual update -> g_xnew
// block (16,8) = 128 threads, each thread owns 2 horizontally adjacent pixels
// tile = 32x8 pixels, halo 1 -> smem region 10 rows x 34 cols per channel
// Weights live in smem DUPLICATED as {w,w} float2 so a single LDS.64 feeds
// the packed FFMA2 directly (no per-FMA register packing).
// ---------------------------------------------------------------------------
extern __shared__ unsigned char smem_raw[];

__global__ void __launch_bounds__(128)
nca_update(const float* __restrict__ x,
           const float* __restrict__ w1,
           const float* __restrict__ b1,
           const float* __restrict__ w2,
           const unsigned int* __restrict__ um)   // mask: 32-bit words, nonzero == true
{
    float2* w1d = (float2*)smem_raw;        // 48*128  = 6144 float2 (49152 B)
    float2* w2d = w1d + 48 * HCH;           // 16*128  = 2048 float2 (16384 B)
    float2* b1d = w2d + 16 * HCH;           // 128 float2 (1024 B)
    float*  xs  = (float*)(b1d + HCH);      // 16*10*36 floats (23040 B)

    const int tid = threadIdx.y * 16 + threadIdx.x;

    // cooperative load of duplicated weights
    for (int i = tid; i < 48 * HCH; i += 128) { float v = w1[i]; w1d[i] = make_float2(v, v); }
    for (int i = tid; i < 16 * HCH; i += 128) { float v = w2[i]; w2d[i] = make_float2(v, v); }
    if (tid < HCH) { float v = b1[tid]; b1d[tid] = make_float2(v, v); }

    const int b  = blockIdx.z;
    const int y0 = blockIdx.y * 8;
    const int x0 = blockIdx.x * 32;

    // x tile + 1-halo: rows y0-1..y0+8, cols x0-1..x0+32, 16 channels
    const float* xb = x + ((long long)b * Cn << 16);
    for (int i = tid; i < 16 * 10 * 34; i += 128) {
        int c   = i / 340;
        int rem = i - c * 340;
        int r   = rem / 34;
        int col = rem - r * 34;
        int gy = y0 - 1 + r;
        int gx = x0 - 1 + col;
        float v = 0.0f;                              // 'SAME' zero padding for conv
        if ((unsigned)gy < Hn && (unsigned)gx < Wn)
            v = xb[(c << 16) + (gy << 8) + gx];
        xs[c * 360 + r * 36 + col] = v;
    }
    __syncthreads();

    const int ly = threadIdx.y;   // 0..7
    const int tx = threadIdx.x;   // 0..15; pixels gxA = x0+2tx, gxB = gxA+1

    // perception: p[3c] = ident, p[3c+1] = sobel_x, p[3c+2] = sobel_y (packed A|B)
    u64 p[48];
#pragma unroll
    for (int c = 0; c < 16; ++c) {
        const float* base = xs + c * 360 + ly * 36 + 2 * tx;  // 3x4 patch top-left
        float v00 = base[0],  v01 = base[1],  v02 = base[2],  v03 = base[3];
        float v10 = base[36], v11 = base[37], v12 = base[38], v13 = base[39];
        float v20 = base[72], v21 = base[73], v22 = base[74], v23 = base[75];
        float sxA = (v02 - v00 + 2.0f * (v12 - v10) + v22 - v20) * 0.125f;
        float sxB = (v03 - v01 + 2.0f * (v13 - v11) + v23 - v21) * 0.125f;
        float syA = (v20 - v00 + 2.0f * (v21 - v01) + v22 - v02) * 0.125f;
        float syB = (v21 - v01 + 2.0f * (v22 - v02) + v23 - v03) * 0.125f;
        p[3 * c + 0] = pack2(v11, v12);
        p[3 * c + 1] = pack2(sxA, sxB);
        p[3 * c + 2] = pack2(syA, syB);
    }

    // fused MLP: dx[k] = sum_o w2[k][o] * relu(b1[o] + sum_c w1[o][c] p[c])
    u64 acc[16];
#pragma unroll
    for (int k = 0; k < 16; ++k) acc[k] = 0ull;

    const u64* w1q = (const u64*)w1d;
    const u64* w2q = (const u64*)w2d;
    const u64* b1q = (const u64*)b1d;

#pragma unroll 1
    for (int o = 0; o < HCH; ++o) {
        const u64* wr = w1q + o * 48;
        u64 h0 = b1q[o];           // 4 partial sums break the latency-4 chain
        u64 h1 = 0ull, h2 = 0ull, h3 = 0ull;
#pragma unroll
        for (int c = 0; c < 48; c += 4) {
            h0 = fma2(wr[c + 0], p[c + 0], h0);
            h1 = fma2(wr[c + 1], p[c + 1], h1);
            h2 = fma2(wr[c + 2], p[c + 2], h2);
            h3 = fma2(wr[c + 3], p[c + 3], h3);
        }
        u64 h = add2(add2(h0, h1), add2(h2, h3));
        float lo, hi;
        unpack2(h, lo, hi);
        lo = fmaxf(lo, 0.0f);
        hi = fmaxf(hi, 0.0f);
        h = pack2(lo, hi);
#pragma unroll
        for (int k = 0; k < 16; ++k)
            acc[k] = fma2(w2q[k * HCH + o], h, acc[k]);
    }

    // epilogue: x_new = x + dx * mask  -> g_xnew
    const int gy    = y0 + ly;
    const int gxA   = x0 + 2 * tx;
    const int mbase = (b << 16) + (gy << 8) + gxA;
    float mA = (um[mbase]     != 0u) ? 1.0f : 0.0f;
    float mB = (um[mbase + 1] != 0u) ? 1.0f : 0.0f;
    u64 mm = pack2(mA, mB);

#pragma unroll
    for (int k = 0; k < 16; ++k) {
        float xA = xs[k * 360 + (ly + 1) * 36 + 1 + 2 * tx];
        float xB = xs[k * 360 + (ly + 1) * 36 + 2 + 2 * tx];
        u64 xn = fma2(acc[k], mm, pack2(xA, xB));
        float lo, hi;
        unpack2(xn, lo, hi);
        *(float2*)(g_xnew + (((b * Cn + k) << 16) + (gy << 8) + gxA)) = make_float2(lo, hi);
    }
}

// ---------------------------------------------------------------------------
// Kernel 2: alive gating.  out = x_new * (maxpool3(x[3])>thr & maxpool3(x_new[3])>thr)
// block (32,8), one pixel per thread, smem tiles of the two channel-3 planes.
// ---------------------------------------------------------------------------
__global__ void __launch_bounds__(256)
nca_mask(const float* __restrict__ x, float* __restrict__ out)
{
    __shared__ float s3[10][36];
    __shared__ float sn3[10][36];

    const int b  = blockIdx.z;
    const int y0 = blockIdx.y * 8;
    const int x0 = blockIdx.x * 32;
    const int tid = threadIdx.y * 32 + threadIdx.x;
    const int plane = ((b * Cn + 3) << 16);

    for (int i = tid; i < 340; i += 256) {
        int r = i / 34, col = i - r * 34;
        int gy = y0 - 1 + r, gx = x0 - 1 + col;
        float v0 = -1e30f, v1 = -1e30f;          // maxpool pads with -inf
        if ((unsigned)gy < Hn && (unsigned)gx < Wn) {
            int idx = plane + (gy << 8) + gx;
            v0 = x[idx];
            v1 = g_xnew[idx];
        }
        s3[r][col]  = v0;
        sn3[r][col] = v1;
    }
    __syncthreads();

    const int ly = threadIdx.y, lx = threadIdx.x;
    float m0 = -1e30f, m1 = -1e30f;
#pragma unroll
    for (int dy = 0; dy < 3; ++dy)
#pragma unroll
        for (int dx = 0; dx < 3; ++dx) {
            m0 = fmaxf(m0, s3[ly + dy][lx + dx]);
            m1 = fmaxf(m1, sn3[ly + dy][lx + dx]);
        }
    float f = (m0 > THRESH && m1 > THRESH) ? 1.0f : 0.0f;

    const int gy = y0 + ly, gx = x0 + lx;
    const int idx = (b << 20) + (gy << 8) + gx;   // b*16*65536 = b<<20
#pragma unroll
    for (int c = 0; c < 16; ++c)
        out[idx + (c << 16)] = g_xnew[idx + (c << 16)] * f;
}

// ---------------------------------------------------------------------------
extern "C" void kernel_launch(void* const* d_in, const int* in_sizes, int n_in,
                              void* d_out, int out_size)
{
    const float* x  = (const float*)d_in[0];
    // d_in[1] = sobel kernel: fixed by construction (ident/sobel_x/sobel_y), hardcoded
    const float* w1 = (const float*)d_in[2];
    const float* b1 = (const float*)d_in[3];
    const float* w2 = (const float*)d_in[4];
    const unsigned int* um = (const unsigned int*)d_in[5];
    float* out = (float*)d_out;

    const int smem1 = (48 * HCH + 16 * HCH + HCH) * (int)sizeof(float2)
                    + 16 * 10 * 36 * (int)sizeof(float);   // 89600 B
    cudaFuncSetAttribute(nca_update, cudaFuncAttributeMaxDynamicSharedMemorySize, smem1);

    dim3 g1(Wn / 32, Hn / 8, Bn), tb1(16, 8);
    nca_update<<<g1, tb1, smem1>>>(x, w1, b1, w2, um);

    dim3 g2(Wn / 32, Hn / 8, Bn), tb2(32, 8);
    nca_mask<<<g2, tb2>>>(x, out);
}

// round 5
// speedup vs baseline: 1.0921x; 1.0921x over previous
#include <cuda_runtime.h>

// ---------------------------------------------------------------------------
// NCA step:  p = depthwise [ident, sobel_x, sobel_y] (16ch -> 48ch)
//            h = relu(W1 p + b1)   (48 -> 128)
//            dx = W2 h             (128 -> 16)
//            x_new = x + dx * update_mask
//            out   = x_new * (maxpool3(x[3])>0.1 & maxpool3(x_new[3])>0.1)
// ---------------------------------------------------------------------------

#define Bn  32
#define Cn  16
#define Hn  256
#define Wn  256
#define HCH 128
#define THRESH 0.1f

// 134 MB scratch for x_new (device global: allocation-free rule)
__device__ float g_xnew[Bn * Cn * Hn * Wn];

typedef unsigned long long u64;

__device__ __forceinline__ u64 fma2(u64 a, u64 b, u64 c) {
    u64 d; asm("fma.rn.f32x2 %0, %1, %2, %3;" : "=l"(d) : "l"(a), "l"(b), "l"(c)); return d;
}
__device__ __forceinline__ u64 add2(u64 a, u64 b) {
    u64 d; asm("add.rn.f32x2 %0, %1, %2;" : "=l"(d) : "l"(a), "l"(b)); return d;
}
__device__ __forceinline__ u64 sub2(u64 a, u64 b) {
    u64 d; asm("sub.rn.f32x2 %0, %1, %2;" : "=l"(d) : "l"(a), "l"(b)); return d;
}
__device__ __forceinline__ u64 mul2(u64 a, u64 b) {
    u64 d; asm("mul.rn.f32x2 %0, %1, %2;" : "=l"(d) : "l"(a), "l"(b)); return d;
}
__device__ __forceinline__ u64 pack2(float lo, float hi) {
    u64 d; asm("mov.b64 %0, {%1, %2};" : "=l"(d) : "f"(lo), "f"(hi)); return d;
}
__device__ __forceinline__ void unpack2(u64 v, float& lo, float& hi) {
    asm("mov.b64 {%0, %1}, %2;" : "=f"(lo), "=f"(hi) : "l"(v));
}
__device__ __forceinline__ float lo2(u64 v) { float a, b; unpack2(v, a, b); return a; }
__device__ __forceinline__ float hi2(u64 v) { float a, b; unpack2(v, a, b); return b; }

// ---------------------------------------------------------------------------
// Kernel 1: perception + MLP + masked residual update -> g_xnew
// block (16,8) = 128 threads, 2 horizontally adjacent pixels per thread.
// Smem phases (overlaid):
//   phase A: xs = x tile + halo (16ch x 10r x 36c floats, 23 KB)
//   phase B (after perception): weights, duplicated {w,w} for packed FFMA2:
//     w1d [128][24] float4 (49152 B) | w2t [128][8] float4 (16384 B) | b1 (1024 B)
// Total 66560 B -> 3 CTAs/SM.
// ---------------------------------------------------------------------------
extern __shared__ unsigned char smem_raw[];

__global__ void __launch_bounds__(128, 3)
nca_update(const float* __restrict__ x,
           const float* __restrict__ w1,
           const float* __restrict__ b1,
           const float* __restrict__ w2,
           const unsigned int* __restrict__ um)   // mask: 32-bit words, nonzero == true
{
    const int tid = threadIdx.y * 16 + threadIdx.x;
    const int b  = blockIdx.z;
    const int y0 = blockIdx.y * 8;
    const int x0 = blockIdx.x * 32;

    // ---- phase A: x tile + 1-halo into xs (overlaid on weight region) ----
    float* xs = (float*)smem_raw;   // [16][10][36], col j <-> global col x0-1+j
    const float* xb = x + ((long long)b * Cn << 16);
    for (int i = tid; i < 16 * 10 * 34; i += 128) {
        int c   = i / 340;
        int rem = i - c * 340;
        int r   = rem / 34;
        int col = rem - r * 34;
        int gy = y0 - 1 + r;
        int gx = x0 - 1 + col;
        float v = 0.0f;                              // 'SAME' zero padding for conv
        if ((unsigned)gy < Hn && (unsigned)gx < Wn)
            v = xb[(c << 16) + (gy << 8) + gx];
        xs[c * 360 + r * 36 + col] = v;
    }
    __syncthreads();

    const int ly = threadIdx.y;   // 0..7
    const int tx = threadIdx.x;   // 0..15; pixels gxA = x0+2tx, gxB = gxA+1

    // ---- perception with aligned LDS.64 + f32x2 sobel ----
    // per row r: a = {v(gxA-1), v(gxA)}, b = {v(gxA+1), v(gxA+2)}  (j = 2tx, 2tx+2)
    const u64 c0125 = pack2(0.125f, 0.125f);
    const u64 c025  = pack2(0.25f, 0.25f);
    u64 p[48];
#pragma unroll
    for (int c = 0; c < 16; ++c) {
        const u64* row0 = (const u64*)(xs + c * 360 + (ly + 0) * 36) + tx;
        const u64* row1 = (const u64*)(xs + c * 360 + (ly + 1) * 36) + tx;
        const u64* row2 = (const u64*)(xs + c * 360 + (ly + 2) * 36) + tx;
        u64 a0 = row0[0], b0 = row0[1];
        u64 a1 = row1[0], b1v = row1[1];
        u64 a2 = row2[0], b2 = row2[1];
        // sx: per-row pair diffs {v_i2-v_i0, v_i3-v_i1}
        u64 r0 = sub2(b0, a0);
        u64 r1 = sub2(b1v, a1);
        u64 r2 = sub2(b2, a2);
        u64 sx = fma2(r1, c025, mul2(add2(r0, r2), c0125));
        // sy: column diffs d_j = v2j - v0j
        u64 da = sub2(a2, a0);          // {d0, d1}
        u64 db = sub2(b2, b0);          // {d2, d3}
        u64 mid = pack2(hi2(da), lo2(db));   // {d1, d2}
        u64 sy = fma2(mid, c025, mul2(add2(da, db), c0125));
        p[3 * c + 0] = pack2(hi2(a1), lo2(b1v));   // ident = x at {gxA, gxB}
        p[3 * c + 1] = sx;
        p[3 * c + 2] = sy;
    }
    __syncthreads();   // xs dead; safe to overwrite with weights

    // ---- phase B: stage duplicated weights into smem ----
    float4* w1f4 = (float4*)smem_raw;                          // [128][24] float4
    float4* w2f4 = (float4*)(smem_raw + 49152);                // [128][8]  float4
    float2* b1d  = (float2*)(smem_raw + 65536);                // [128]

    const float4* w1g = (const float4*)w1;   // 6144 floats = 1536 float4
    for (int i = tid; i < 1536; i += 128) {
        float4 v = w1g[i];
        w1f4[2 * i]     = make_float4(v.x, v.x, v.y, v.y);
        w1f4[2 * i + 1] = make_float4(v.z, v.z, v.w, v.w);
    }
    {
        float2* w2t = (float2*)w2f4;          // [o][k] duplicated
        for (int i = tid; i < 2048; i += 128) {
            int o = i >> 4, k = i & 15;
            float v = w2[k * HCH + o];
            w2t[i] = make_float2(v, v);
        }
    }
    if (tid < HCH) { float v = b1[tid]; b1d[tid] = make_float2(v, v); }
    __syncthreads();

    // mask load early (hide latency behind MLP)
    const int gy    = y0 + ly;
    const int gxA   = x0 + 2 * tx;
    const uint2 mv  = *(const uint2*)(um + ((b << 16) + (gy << 8) + gxA));
    const u64 mm = pack2(mv.x ? 1.0f : 0.0f, mv.y ? 1.0f : 0.0f);

    // ---- fused MLP ----
    u64 acc[16];
#pragma unroll
    for (int k = 0; k < 16; ++k) acc[k] = 0ull;
    const u64* b1q = (const u64*)b1d;

#pragma unroll 1
    for (int o = 0; o < HCH; ++o) {
        const float4* wr = w1f4 + o * 24;
        u64 h0 = b1q[o], h1 = 0ull, h2 = 0ull, h3 = 0ull;
#pragma unroll
        for (int i = 0; i < 24; i += 2) {
            float4 qa = wr[i];
            float4 qb = wr[i + 1];
            h0 = fma2(pack2(qa.x, qa.y), p[2 * i + 0], h0);
            h1 = fma2(pack2(qa.z, qa.w), p[2 * i + 1], h1);
            h2 = fma2(pack2(qb.x, qb.y), p[2 * i + 2], h2);
            h3 = fma2(pack2(qb.z, qb.w), p[2 * i + 3], h3);
        }
        u64 h = add2(add2(h0, h1), add2(h2, h3));
        float lo, hi;
        unpack2(h, lo, hi);
        h = pack2(fmaxf(lo, 0.0f), fmaxf(hi, 0.0f));

        const float4* w2r = w2f4 + o * 8;
#pragma unroll
        for (int k4 = 0; k4 < 8; ++k4) {
            float4 q = w2r[k4];
            acc[2 * k4 + 0] = fma2(pack2(q.x, q.y), h, acc[2 * k4 + 0]);
            acc[2 * k4 + 1] = fma2(pack2(q.z, q.w), h, acc[2 * k4 + 1]);
        }
    }

    // ---- epilogue: x_new = x + dx*mask -> g_xnew (x values live in p[3c]) ----
#pragma unroll
    for (int k = 0; k < 16; ++k) {
        u64 xn = fma2(acc[k], mm, p[3 * k]);
        float lo, hi;
        unpack2(xn, lo, hi);
        *(float2*)(g_xnew + (((b * Cn + k) << 16) + (gy << 8) + gxA)) = make_float2(lo, hi);
    }
}

// ---------------------------------------------------------------------------
// Kernel 2: alive gating.  out = x_new * (maxpool3(x[3])>thr & maxpool3(x_new[3])>thr)
// block (32,8), tile 128x8, 4 px/thread via float4; column-max reuse.
// ---------------------------------------------------------------------------
__global__ void __launch_bounds__(256)
nca_mask(const float* __restrict__ x, float* __restrict__ out)
{
    __shared__ float s3[10][136];
    __shared__ float sn3[10][136];

    const int b  = blockIdx.z;
    const int y0 = blockIdx.y * 8;
    const int x0 = blockIdx.x * 128;
    const int tid = threadIdx.y * 32 + threadIdx.x;
    const int plane = ((b * Cn + 3) << 16);

    for (int i = tid; i < 10 * 130; i += 256) {
        int r = i / 130, j = i - r * 130;
        int gy = y0 - 1 + r, gx = x0 - 1 + j;
        float v0 = -1e30f, v1 = -1e30f;          // maxpool pads with -inf
        if ((unsigned)gy < Hn && (unsigned)gx < Wn) {
            int idx = plane + (gy << 8) + gx;
            v0 = x[idx];
            v1 = g_xnew[idx];
        }
        s3[r][j]  = v0;
        sn3[r][j] = v1;
    }
    __syncthreads();

    const int ty = threadIdx.y, tx = threadIdx.x;
    // pixel gx = x0+4tx+i  <->  smem col j = 4tx+1+i; window cols j-1..j+1
    float c0[6], c1[6];
#pragma unroll
    for (int jj = 0; jj < 6; ++jj) {
        int j = 4 * tx + jj;
        c0[jj] = fmaxf(fmaxf(s3[ty][j],  s3[ty + 1][j]),  s3[ty + 2][j]);
        c1[jj] = fmaxf(fmaxf(sn3[ty][j], sn3[ty + 1][j]), sn3[ty + 2][j]);
    }
    float f[4];
#pragma unroll
    for (int i = 0; i < 4; ++i) {
        float m0 = fmaxf(fmaxf(c0[i], c0[i + 1]), c0[i + 2]);
        float m1 = fmaxf(fmaxf(c1[i], c1[i + 1]), c1[i + 2]);
        f[i] = (m0 > THRESH && m1 > THRESH) ? 1.0f : 0.0f;
    }

    const int gy = y0 + ty, gxA = x0 + 4 * tx;
    const int idx = (b << 20) + (gy << 8) + gxA;
#pragma unroll
    for (int c = 0; c < 16; ++c) {
        float4 v = *(const float4*)(g_xnew + idx + (c << 16));
        v.x *= f[0]; v.y *= f[1]; v.z *= f[2]; v.w *= f[3];
        *(float4*)(out + idx + (c << 16)) = v;
    }
}

// ---------------------------------------------------------------------------
extern "C" void kernel_launch(void* const* d_in, const int* in_sizes, int n_in,
                              void* d_out, int out_size)
{
    const float* x  = (const float*)d_in[0];
    // d_in[1] = sobel kernel: fixed by construction, hardcoded
    const float* w1 = (const float*)d_in[2];
    const float* b1 = (const float*)d_in[3];
    const float* w2 = (const float*)d_in[4];
    const unsigned int* um = (const unsigned int*)d_in[5];
    float* out = (float*)d_out;

    const int smem1 = 49152 + 16384 + 1024;   // 66560 B
    cudaFuncSetAttribute(nca_update, cudaFuncAttributeMaxDynamicSharedMemorySize, smem1);

    dim3 g1(Wn / 32, Hn / 8, Bn), tb1(16, 8);
    nca_update<<<g1, tb1, smem1>>>(x, w1, b1, w2, um);

    dim3 g2(Wn / 128, Hn / 8, Bn), tb2(32, 8);
    nca_mask<<<g2, tb2>>>(x, out);
}